// round 1
// baseline (speedup 1.0000x reference)
#include <cuda_runtime.h>

#define Hh 256
#define Ww 704
#define HW (Hh * Ww)        // 180224
#define CIMG 256
#define NCOUT 131

// ---------------- scratch (static device globals; no allocation) -------------
__device__ float g_u[9 * 131];      // per-tap folded rd2^T * sp_w vectors (also v for level 2)
__device__ float g_v0[9 * 35];      // level-0 per-point weight vectors
__device__ float g_v1[9 * 67];      // level-1 per-point weight vectors
__device__ float g_constS[9];       // per-tap constant (bias-fold)
__device__ float g_wsum[9];         // per-tap channel-sum of sp_w (gated broadcast fold)
__device__ float g_S9[9 * HW];      // 9 scalar planes: tap-dot of pt_img2 at each cell
__device__ float g_gated[HW];       // rd3 conv of img_feat
__device__ float g_att[HW];         // sigmoid attention

// ---------------- K0a: u_t = W2^T wvec_t ------------------------------------
__global__ void k0a(const float* __restrict__ rd2_w, const float* __restrict__ sp_w) {
    int id = blockIdx.x * blockDim.x + threadIdx.x;
    if (id >= 9 * 131) return;
    int t = id / 131, i = id % 131;
    float s = 0.f;
    for (int ch = 0; ch < 131; ch++)
        s += rd2_w[ch * 131 + i] * sp_w[ch * 9 + t];
    g_u[id] = s;   // layout [t][i]
}

// ---------------- K0b: v0, v1, per-tap constants -----------------------------
__global__ void k0b(const float* __restrict__ rd0_w, const float* __restrict__ rd1_w,
                    const float* __restrict__ rd0_b, const float* __restrict__ rd1_b,
                    const float* __restrict__ rd2_b, const float* __restrict__ sp_w) {
    int id = blockIdx.x * blockDim.x + threadIdx.x;
    if (id < 9 * 35) {
        int t = id / 35, j = id % 35;
        float s = 0.f;
        for (int o = 0; o < 131; o++) s += rd0_w[o * 35 + j] * g_u[t * 131 + o];
        g_v0[id] = s;
    } else if (id < 9 * 35 + 9 * 67) {
        int id2 = id - 9 * 35;
        int t = id2 / 67, j = id2 % 67;
        float s = 0.f;
        for (int o = 0; o < 131; o++) s += rd1_w[o * 67 + j] * g_u[t * 131 + o];
        g_v1[id2] = s;
    } else if (id < 9 * 35 + 9 * 67 + 9) {
        int t = id - 9 * 35 - 9 * 67;
        float s = 0.f, wsum = 0.f;
        for (int o = 0; o < 131; o++) {
            s += g_u[t * 131 + o] * (rd0_b[o] + rd1_b[o]) + sp_w[o * 9 + t] * rd2_b[o];
            wsum += sp_w[o * 9 + t];
        }
        g_constS[t] = s;
        g_wsum[t] = wsum;
    }
}

// ---------------- K1: init S9 planes to per-tap constant ---------------------
__global__ void k1_init() {
    int idx = blockIdx.x * blockDim.x + threadIdx.x;
    if (idx < 9 * HW) g_S9[idx] = g_constS[idx / HW];
}

// ---------------- K2: sparse point scatter (warp per point) ------------------
// Cells are unique within a level and levels run sequentially -> plain +=, deterministic.
template <int CH>
__global__ void k_scatter(const float* __restrict__ feat, const float* __restrict__ coord,
                          const int* __restrict__ grid, int N) {
    const int D = CH + 3;
    const float* v = (CH == 32) ? g_v0 : (CH == 64) ? g_v1 : g_u;
    int w = (blockIdx.x * blockDim.x + threadIdx.x) >> 5;
    int lane = threadIdx.x & 31;
    if (w >= N) return;
    float acc[9];
#pragma unroll
    for (int t = 0; t < 9; t++) acc[t] = 0.f;
#pragma unroll
    for (int c = lane; c < D; c += 32) {
        float x = (c < CH) ? feat[w * CH + c] : coord[w * 3 + (c - CH)];
#pragma unroll
        for (int t = 0; t < 9; t++) acc[t] += v[t * D + c] * x;
    }
#pragma unroll
    for (int off = 16; off; off >>= 1) {
#pragma unroll
        for (int t = 0; t < 9; t++)
            acc[t] += __shfl_down_sync(0xffffffffu, acc[t], off);
    }
    if (lane == 0) {
        int cx = grid[2 * w], cy = grid[2 * w + 1];
        int cell = cy * Ww + cx;
#pragma unroll
        for (int t = 0; t < 9; t++) g_S9[t * HW + cell] += acc[t];
    }
}

// ---------------- K3: gated = rd3_w . img_feat + rd3_b (per pixel) -----------
__global__ void k_gated(const float* __restrict__ img, const float* __restrict__ w3,
                        const float* __restrict__ b3) {
    int p2 = blockIdx.x * blockDim.x + threadIdx.x;   // pixel pair index
    if (p2 >= HW / 2) return;
    const float2* img2 = (const float2*)img;
    float sx = 0.f, sy = 0.f;
#pragma unroll 8
    for (int ch = 0; ch < CIMG; ch++) {
        float w = w3[ch];
        float2 vv = img2[ch * (HW / 2) + p2];
        sx += w * vv.x;
        sy += w * vv.y;
    }
    float b = b3[0];
    float2 o;
    o.x = sx + b;
    o.y = sy + b;
    ((float2*)g_gated)[p2] = o;
}

// ---------------- K4a: attention plane ---------------------------------------
__global__ void k_att(const float* __restrict__ sp_b) {
    int p = blockIdx.x * blockDim.x + threadIdx.x;
    if (p >= HW) return;
    int r = p / Ww, c = p % Ww;
    float acc = sp_b[0];
#pragma unroll
    for (int t = 0; t < 9; t++) {
        int rr = r + t / 3 - 1;
        int cc = c + t % 3 - 1;
        if ((unsigned)rr < Hh && (unsigned)cc < Ww) {
            int q = rr * Ww + cc;
            acc += g_wsum[t] * g_gated[q] + g_S9[t * HW + q];
        }
    }
    g_att[p] = 1.f / (1.f + __expf(-acc));
}

// ---------------- K4b: out = img_feat * attention (broadcast) ----------------
// blockDim 256; gridDim = 176 (pixel-quad blocks) * 32 (channel groups of 8)
__global__ void k_mul(const float* __restrict__ img, float* __restrict__ out) {
    int bq = blockIdx.x % 176;
    int g = blockIdx.x / 176;
    int q4 = bq * 256 + threadIdx.x;   // 0 .. 45055
    const float4* img4 = (const float4*)img;
    float4* out4 = (float4*)out;
    float4 a = ((const float4*)g_att)[q4];
#pragma unroll
    for (int k = 0; k < 8; k++) {
        int ch = g * 8 + k;
        float4 v = img4[ch * (HW / 4) + q4];
        v.x *= a.x; v.y *= a.y; v.z *= a.z; v.w *= a.w;
        out4[ch * (HW / 4) + q4] = v;
    }
}

extern "C" void kernel_launch(void* const* d_in, const int* in_sizes, int n_in,
                              void* d_out, int out_size) {
    const float* img   = (const float*)d_in[0];
    const float* f0    = (const float*)d_in[1];
    const float* c0    = (const float*)d_in[2];
    const int*   gr0   = (const int*)d_in[3];
    const float* f1    = (const float*)d_in[4];
    const float* c1    = (const float*)d_in[5];
    const int*   gr1   = (const int*)d_in[6];
    const float* f2    = (const float*)d_in[7];
    const float* c2    = (const float*)d_in[8];
    const int*   gr2   = (const int*)d_in[9];
    const float* rd0_w = (const float*)d_in[10];
    const float* rd0_b = (const float*)d_in[11];
    const float* rd1_w = (const float*)d_in[12];
    const float* rd1_b = (const float*)d_in[13];
    const float* rd2_w = (const float*)d_in[14];
    const float* rd2_b = (const float*)d_in[15];
    const float* rd3_w = (const float*)d_in[16];
    const float* rd3_b = (const float*)d_in[17];
    const float* sp_w  = (const float*)d_in[18];
    const float* sp_b  = (const float*)d_in[19];
    float* out = (float*)d_out;

    int N0 = in_sizes[3] / 2;
    int N1 = in_sizes[6] / 2;
    int N2 = in_sizes[9] / 2;

    // weight folding (tiny)
    k0a<<<(9 * 131 + 255) / 256, 256>>>(rd2_w, sp_w);
    k0b<<<(9 * 35 + 9 * 67 + 9 + 255) / 256, 256>>>(rd0_w, rd1_w, rd0_b, rd1_b, rd2_b, sp_w);

    // init 9 scalar planes to per-tap constants
    k1_init<<<(9 * HW + 255) / 256, 256>>>();

    // sparse scatters (sequential -> deterministic plain +=)
    k_scatter<32><<<(N0 * 32 + 255) / 256, 256>>>(f0, c0, gr0, N0);
    k_scatter<64><<<(N1 * 32 + 255) / 256, 256>>>(f1, c1, gr1, N1);
    k_scatter<128><<<(N2 * 32 + 255) / 256, 256>>>(f2, c2, gr2, N2);

    // gated plane (reads img_feat once)
    k_gated<<<(HW / 2 + 255) / 256, 256>>>(img, rd3_w, rd3_b);

    // attention plane
    k_att<<<(HW + 255) / 256, 256>>>(sp_b);

    // final broadcast multiply (reads img_feat again, writes output)
    k_mul<<<176 * 32, 256>>>(img, out);
}

// round 2
// speedup vs baseline: 1.1124x; 1.1124x over previous
#include <cuda_runtime.h>

#define Hh 256
#define Ww 704
#define HW (Hh * Ww)        // 180224
#define CIMG 256

// ---------------- scratch (static device globals; no allocation) -------------
__device__ float g_u[9 * 131];      // per-tap folded rd2^T * sp_w vectors (also v for level 2)
__device__ float g_v0[9 * 35];      // level-0 per-point weight vectors
__device__ float g_v1[9 * 67];      // level-1 per-point weight vectors
__device__ float g_constS[9];       // per-tap constant (bias-fold)
__device__ float g_wsum[9];         // per-tap channel-sum of sp_w (gated broadcast fold)
__device__ float g_S9[HW * 9];      // per-cell 9 tap-dots, interleaved [cell][tap]
__device__ float g_gated[HW];       // rd3 conv of img_feat
__device__ float g_att[HW];         // sigmoid attention

// ---------------- K0a: u_t = W2^T wvec_t ------------------------------------
__global__ void k0a(const float* __restrict__ rd2_w, const float* __restrict__ sp_w) {
    int id = blockIdx.x * blockDim.x + threadIdx.x;
    if (id >= 9 * 131) return;
    int t = id / 131, i = id % 131;
    float s = 0.f;
    for (int ch = 0; ch < 131; ch++)
        s += rd2_w[ch * 131 + i] * sp_w[ch * 9 + t];
    g_u[id] = s;   // layout [t][i]
}

// ---------------- K0b: v0, v1, per-tap constants -----------------------------
__global__ void k0b(const float* __restrict__ rd0_w, const float* __restrict__ rd1_w,
                    const float* __restrict__ rd0_b, const float* __restrict__ rd1_b,
                    const float* __restrict__ rd2_b, const float* __restrict__ sp_w) {
    int id = blockIdx.x * blockDim.x + threadIdx.x;
    if (id < 9 * 35) {
        int t = id / 35, j = id % 35;
        float s = 0.f;
        for (int o = 0; o < 131; o++) s += rd0_w[o * 35 + j] * g_u[t * 131 + o];
        g_v0[id] = s;
    } else if (id < 9 * 35 + 9 * 67) {
        int id2 = id - 9 * 35;
        int t = id2 / 67, j = id2 % 67;
        float s = 0.f;
        for (int o = 0; o < 131; o++) s += rd1_w[o * 67 + j] * g_u[t * 131 + o];
        g_v1[id2] = s;
    } else if (id < 9 * 35 + 9 * 67 + 9) {
        int t = id - 9 * 35 - 9 * 67;
        float s = 0.f, wsum = 0.f;
        for (int o = 0; o < 131; o++) {
            s += g_u[t * 131 + o] * (rd0_b[o] + rd1_b[o]) + sp_w[o * 9 + t] * rd2_b[o];
            wsum += sp_w[o * 9 + t];
        }
        g_constS[t] = s;
        g_wsum[t] = wsum;
    }
}

// ---------------- K1: zero S9 (float4 fill) ----------------------------------
__global__ void k1_zero() {
    int idx = blockIdx.x * blockDim.x + threadIdx.x;
    if (idx < HW * 9 / 4)
        ((float4*)g_S9)[idx] = make_float4(0.f, 0.f, 0.f, 0.f);
}

// ---------------- K2: sparse point scatter (thread per point) ----------------
// Cells unique within a level, levels sequential -> plain += is deterministic.
template <int CH>
__global__ void k_scatter(const float* __restrict__ feat, const float* __restrict__ coord,
                          const int* __restrict__ grid, int N) {
    const int D = CH + 3;
    __shared__ float sv[9 * (CH + 3)];
    const float* vsrc = (CH == 32) ? g_v0 : (CH == 64) ? g_v1 : g_u;
    for (int i = threadIdx.x; i < 9 * D; i += blockDim.x) sv[i] = vsrc[i];
    __syncthreads();

    int p = blockIdx.x * blockDim.x + threadIdx.x;
    if (p >= N) return;

    float acc[9];
#pragma unroll
    for (int t = 0; t < 9; t++) acc[t] = 0.f;

    const float4* f4 = (const float4*)(feat + (size_t)p * CH);
#pragma unroll 4
    for (int i = 0; i < CH / 4; i++) {
        float4 x = f4[i];
#pragma unroll
        for (int t = 0; t < 9; t++) {
            const float* vt = &sv[t * D + 4 * i];
            acc[t] += vt[0] * x.x + vt[1] * x.y + vt[2] * x.z + vt[3] * x.w;
        }
    }
    float cx0 = coord[3 * p], cx1 = coord[3 * p + 1], cx2 = coord[3 * p + 2];
#pragma unroll
    for (int t = 0; t < 9; t++)
        acc[t] += sv[t * D + CH] * cx0 + sv[t * D + CH + 1] * cx1 + sv[t * D + CH + 2] * cx2;

    int gx = grid[2 * p], gy = grid[2 * p + 1];
    int base = (gy * Ww + gx) * 9;
#pragma unroll
    for (int t = 0; t < 9; t++) g_S9[base + t] += acc[t];
}

// ---------------- K3: gated = rd3_w . img_feat + rd3_b (float4 per thread) ---
__global__ void k_gated(const float* __restrict__ img, const float* __restrict__ w3,
                        const float* __restrict__ b3) {
    int p4 = blockIdx.x * blockDim.x + threadIdx.x;   // pixel-quad index
    if (p4 >= HW / 4) return;
    const float4* img4 = (const float4*)img;
    float4 s = make_float4(0.f, 0.f, 0.f, 0.f);
#pragma unroll 8
    for (int ch = 0; ch < CIMG; ch++) {
        float w = __ldg(&w3[ch]);
        float4 v = img4[ch * (HW / 4) + p4];
        s.x += w * v.x; s.y += w * v.y; s.z += w * v.z; s.w += w * v.w;
    }
    float b = b3[0];
    s.x += b; s.y += b; s.z += b; s.w += b;
    ((float4*)g_gated)[p4] = s;
}

// ---------------- K4a: attention plane ---------------------------------------
__global__ void k_att(const float* __restrict__ sp_b) {
    int p = blockIdx.x * blockDim.x + threadIdx.x;
    if (p >= HW) return;
    int r = p / Ww, c = p % Ww;
    float acc = sp_b[0];
#pragma unroll
    for (int t = 0; t < 9; t++) {
        int rr = r + t / 3 - 1;
        int cc = c + t % 3 - 1;
        if ((unsigned)rr < Hh && (unsigned)cc < Ww) {
            int q = rr * Ww + cc;
            acc += g_wsum[t] * g_gated[q] + g_S9[q * 9 + t] + g_constS[t];
        }
    }
    g_att[p] = 1.f / (1.f + __expf(-acc));
}

// ---------------- K4b: out = img_feat * attention (broadcast) ----------------
// blockDim 256; gridDim = 176 (pixel-quad blocks) * 32 (channel groups of 8)
__global__ void k_mul(const float* __restrict__ img, float* __restrict__ out) {
    int bq = blockIdx.x % 176;
    int g = blockIdx.x / 176;
    int q4 = bq * 256 + threadIdx.x;   // 0 .. 45055
    const float4* img4 = (const float4*)img;
    float4* out4 = (float4*)out;
    float4 a = ((const float4*)g_att)[q4];
#pragma unroll
    for (int k = 0; k < 8; k++) {
        int ch = g * 8 + k;
        float4 v = img4[ch * (HW / 4) + q4];
        v.x *= a.x; v.y *= a.y; v.z *= a.z; v.w *= a.w;
        out4[ch * (HW / 4) + q4] = v;
    }
}

extern "C" void kernel_launch(void* const* d_in, const int* in_sizes, int n_in,
                              void* d_out, int out_size) {
    const float* img   = (const float*)d_in[0];
    const float* f0    = (const float*)d_in[1];
    const float* c0    = (const float*)d_in[2];
    const int*   gr0   = (const int*)d_in[3];
    const float* f1    = (const float*)d_in[4];
    const float* c1    = (const float*)d_in[5];
    const int*   gr1   = (const int*)d_in[6];
    const float* f2    = (const float*)d_in[7];
    const float* c2    = (const float*)d_in[8];
    const int*   gr2   = (const int*)d_in[9];
    const float* rd0_w = (const float*)d_in[10];
    const float* rd0_b = (const float*)d_in[11];
    const float* rd1_w = (const float*)d_in[12];
    const float* rd1_b = (const float*)d_in[13];
    const float* rd2_w = (const float*)d_in[14];
    const float* rd2_b = (const float*)d_in[15];
    const float* rd3_w = (const float*)d_in[16];
    const float* rd3_b = (const float*)d_in[17];
    const float* sp_w  = (const float*)d_in[18];
    const float* sp_b  = (const float*)d_in[19];
    float* out = (float*)d_out;

    int N0 = in_sizes[3] / 2;
    int N1 = in_sizes[6] / 2;
    int N2 = in_sizes[9] / 2;

    // weight folding (tiny)
    k0a<<<(9 * 131 + 255) / 256, 256>>>(rd2_w, sp_w);
    k0b<<<(9 * 35 + 9 * 67 + 9 + 255) / 256, 256>>>(rd0_w, rd1_w, rd0_b, rd1_b, rd2_b, sp_w);

    // zero the interleaved S9 planes
    k1_zero<<<(HW * 9 / 4 + 255) / 256, 256>>>();

    // sparse scatters (sequential -> deterministic plain +=)
    k_scatter<32><<<(N0 + 255) / 256, 256>>>(f0, c0, gr0, N0);
    k_scatter<64><<<(N1 + 255) / 256, 256>>>(f1, c1, gr1, N1);
    k_scatter<128><<<(N2 + 255) / 256, 256>>>(f2, c2, gr2, N2);

    // gated plane (reads img_feat once)
    k_gated<<<(HW / 4 + 255) / 256, 256>>>(img, rd3_w, rd3_b);

    // attention plane
    k_att<<<(HW + 255) / 256, 256>>>(sp_b);

    // final broadcast multiply (reads img_feat again, writes output)
    k_mul<<<176 * 32, 256>>>(img, out);
}

// round 3
// speedup vs baseline: 1.4960x; 1.3448x over previous
#include <cuda_runtime.h>

#define Hh 256
#define Ww 704
#define HW (Hh * Ww)        // 180224
#define CIMG 256
#define GB 176              // gated blocks: HW/4/256

// ---------------- scratch (static device globals; no allocation) -------------
__device__ float g_u[9 * 131];      // per-tap folded rd2^T * sp_w vectors (also v for level 2)
__device__ float g_v0[9 * 35];      // level-0 per-point weight vectors
__device__ float g_v1[9 * 67];      // level-1 per-point weight vectors
__device__ float g_constS[9];       // per-tap constant (bias-fold)
__device__ float g_wsum[9];         // per-tap channel-sum of sp_w (gated broadcast fold)
__device__ float g_S9[HW * 9];      // per-cell 9 tap-dots, interleaved [cell][tap]
__device__ float g_gated[HW];       // rd3 conv of img_feat
__device__ float g_att[HW];         // sigmoid attention

// ---------------- K0a: u_t = W2^T wvec_t ------------------------------------
__global__ void k0a(const float* __restrict__ rd2_w, const float* __restrict__ sp_w) {
    int id = blockIdx.x * blockDim.x + threadIdx.x;
    if (id >= 9 * 131) return;
    int t = id / 131, i = id % 131;
    float s = 0.f;
    for (int ch = 0; ch < 131; ch++)
        s += rd2_w[ch * 131 + i] * sp_w[ch * 9 + t];
    g_u[id] = s;   // layout [t][i]
}

// ---------------- K0b + zero-fill fused --------------------------------------
// blocks 0..3: weight folding (927 work items); blocks 4..: zero S9 float4s
__global__ void k0bz(const float* __restrict__ rd0_w, const float* __restrict__ rd1_w,
                     const float* __restrict__ rd0_b, const float* __restrict__ rd1_b,
                     const float* __restrict__ rd2_b, const float* __restrict__ sp_w) {
    if (blockIdx.x >= 4) {
        int idx = (blockIdx.x - 4) * blockDim.x + threadIdx.x;
        if (idx < HW * 9 / 4)
            ((float4*)g_S9)[idx] = make_float4(0.f, 0.f, 0.f, 0.f);
        return;
    }
    int id = blockIdx.x * blockDim.x + threadIdx.x;
    if (id < 9 * 35) {
        int t = id / 35, j = id % 35;
        float s = 0.f;
        for (int o = 0; o < 131; o++) s += rd0_w[o * 35 + j] * g_u[t * 131 + o];
        g_v0[id] = s;
    } else if (id < 9 * 35 + 9 * 67) {
        int id2 = id - 9 * 35;
        int t = id2 / 67, j = id2 % 67;
        float s = 0.f;
        for (int o = 0; o < 131; o++) s += rd1_w[o * 67 + j] * g_u[t * 131 + o];
        g_v1[id2] = s;
    } else if (id < 9 * 35 + 9 * 67 + 9) {
        int t = id - 9 * 35 - 9 * 67;
        float s = 0.f, wsum = 0.f;
        for (int o = 0; o < 131; o++) {
            s += g_u[t * 131 + o] * (rd0_b[o] + rd1_b[o]) + sp_w[o * 9 + t] * rd2_b[o];
            wsum += sp_w[o * 9 + t];
        }
        g_constS[t] = s;
        g_wsum[t] = wsum;
    }
}

// ---------------- scatter body (thread per point, REDG atomics) --------------
template <int CH>
__device__ __forceinline__ void scatter_body(const float* __restrict__ feat,
                                             const float* __restrict__ coord,
                                             const int* __restrict__ grid,
                                             int N, int pblock, float* sv) {
    const int D = CH + 3;
    const float* vsrc = (CH == 32) ? g_v0 : (CH == 64) ? g_v1 : g_u;
    for (int i = threadIdx.x; i < 9 * D; i += blockDim.x) sv[i] = vsrc[i];
    __syncthreads();

    int p = pblock * blockDim.x + threadIdx.x;
    if (p >= N) return;

    float acc[9];
#pragma unroll
    for (int t = 0; t < 9; t++) acc[t] = 0.f;

    const float4* f4 = (const float4*)(feat + (size_t)p * CH);
#pragma unroll 4
    for (int i = 0; i < CH / 4; i++) {
        float4 x = f4[i];
#pragma unroll
        for (int t = 0; t < 9; t++) {
            const float* vt = &sv[t * D + 4 * i];
            acc[t] += vt[0] * x.x + vt[1] * x.y + vt[2] * x.z + vt[3] * x.w;
        }
    }
    float cx0 = coord[3 * p], cx1 = coord[3 * p + 1], cx2 = coord[3 * p + 2];
#pragma unroll
    for (int t = 0; t < 9; t++)
        acc[t] += sv[t * D + CH] * cx0 + sv[t * D + CH + 1] * cx1 + sv[t * D + CH + 2] * cx2;

    int gx = grid[2 * p], gy = grid[2 * p + 1];
    int base = (gy * Ww + gx) * 9;
#pragma unroll
    for (int t = 0; t < 9; t++) atomicAdd(&g_S9[base + t], acc[t]);
}

// ---------------- fused main: gated plane + all three scatters ---------------
__global__ void k_main(const float* __restrict__ img, const float* __restrict__ w3,
                       const float* __restrict__ b3,
                       const float* __restrict__ f0, const float* __restrict__ c0,
                       const int* __restrict__ gr0, int N0,
                       const float* __restrict__ f1, const float* __restrict__ c1,
                       const int* __restrict__ gr1, int N1,
                       const float* __restrict__ f2, const float* __restrict__ c2,
                       const int* __restrict__ gr2, int N2) {
    __shared__ float sv[9 * 131];
    int b = blockIdx.x;
    if (b < GB) {
        // gated: rd3 1x1 conv, float4 per thread
        int p4 = b * blockDim.x + threadIdx.x;   // < HW/4 exactly (176*256)
        const float4* img4 = (const float4*)img;
        float4 s = make_float4(0.f, 0.f, 0.f, 0.f);
#pragma unroll 8
        for (int ch = 0; ch < CIMG; ch++) {
            float w = __ldg(&w3[ch]);
            float4 v = img4[ch * (HW / 4) + p4];
            s.x += w * v.x; s.y += w * v.y; s.z += w * v.z; s.w += w * v.w;
        }
        float bb = b3[0];
        s.x += bb; s.y += bb; s.z += bb; s.w += bb;
        ((float4*)g_gated)[p4] = s;
        return;
    }
    b -= GB;
    int S0 = (N0 + 255) >> 8, S1 = (N1 + 255) >> 8;
    if (b < S0)            scatter_body<32>(f0, c0, gr0, N0, b, sv);
    else if (b < S0 + S1)  scatter_body<64>(f1, c1, gr1, N1, b - S0, sv);
    else                   scatter_body<128>(f2, c2, gr2, N2, b - S0 - S1, sv);
}

// ---------------- K4a: attention plane ---------------------------------------
__global__ void k_att(const float* __restrict__ sp_b) {
    int p = blockIdx.x * blockDim.x + threadIdx.x;
    if (p >= HW) return;
    int r = p / Ww, c = p % Ww;
    float acc = sp_b[0];
#pragma unroll
    for (int t = 0; t < 9; t++) {
        int rr = r + t / 3 - 1;
        int cc = c + t % 3 - 1;
        if ((unsigned)rr < Hh && (unsigned)cc < Ww) {
            int q = rr * Ww + cc;
            acc += g_wsum[t] * g_gated[q] + g_S9[q * 9 + t] + g_constS[t];
        }
    }
    g_att[p] = 1.f / (1.f + __expf(-acc));
}

// ---------------- K4b: out = img_feat * attention (broadcast) ----------------
__global__ void k_mul(const float* __restrict__ img, float* __restrict__ out) {
    int bq = blockIdx.x % 176;
    int g = blockIdx.x / 176;
    int q4 = bq * 256 + threadIdx.x;   // 0 .. 45055
    const float4* img4 = (const float4*)img;
    float4* out4 = (float4*)out;
    float4 a = ((const float4*)g_att)[q4];
#pragma unroll
    for (int k = 0; k < 8; k++) {
        int ch = g * 8 + k;
        float4 v = img4[ch * (HW / 4) + q4];
        v.x *= a.x; v.y *= a.y; v.z *= a.z; v.w *= a.w;
        out4[ch * (HW / 4) + q4] = v;
    }
}

extern "C" void kernel_launch(void* const* d_in, const int* in_sizes, int n_in,
                              void* d_out, int out_size) {
    const float* img   = (const float*)d_in[0];
    const float* f0    = (const float*)d_in[1];
    const float* c0    = (const float*)d_in[2];
    const int*   gr0   = (const int*)d_in[3];
    const float* f1    = (const float*)d_in[4];
    const float* c1    = (const float*)d_in[5];
    const int*   gr1   = (const int*)d_in[6];
    const float* f2    = (const float*)d_in[7];
    const float* c2    = (const float*)d_in[8];
    const int*   gr2   = (const int*)d_in[9];
    const float* rd0_w = (const float*)d_in[10];
    const float* rd0_b = (const float*)d_in[11];
    const float* rd1_w = (const float*)d_in[12];
    const float* rd1_b = (const float*)d_in[13];
    const float* rd2_w = (const float*)d_in[14];
    const float* rd2_b = (const float*)d_in[15];
    const float* rd3_w = (const float*)d_in[16];
    const float* rd3_b = (const float*)d_in[17];
    const float* sp_w  = (const float*)d_in[18];
    const float* sp_b  = (const float*)d_in[19];
    float* out = (float*)d_out;

    int N0 = in_sizes[3] / 2;
    int N1 = in_sizes[6] / 2;
    int N2 = in_sizes[9] / 2;

    // weight folding stage 1 (tiny)
    k0a<<<(9 * 131 + 255) / 256, 256>>>(rd2_w, sp_w);

    // weight folding stage 2 + zero S9
    k0bz<<<4 + (HW * 9 / 4 + 255) / 256, 256>>>(rd0_w, rd1_w, rd0_b, rd1_b, rd2_b, sp_w);

    // fused: gated plane (BW-bound) overlapped with all scatters (latency-bound)
    int S0 = (N0 + 255) / 256, S1 = (N1 + 255) / 256, S2 = (N2 + 255) / 256;
    k_main<<<GB + S0 + S1 + S2, 256>>>(img, rd3_w, rd3_b,
                                       f0, c0, gr0, N0,
                                       f1, c1, gr1, N1,
                                       f2, c2, gr2, N2);

    // attention plane (L2-resident inputs)
    k_att<<<(HW + 255) / 256, 256>>>(sp_b);

    // final broadcast multiply (reads img_feat again, writes output)
    k_mul<<<176 * 32, 256>>>(img, out);
}